// round 16
// baseline (speedup 1.0000x reference)
#include <cuda_runtime.h>
#include <cuda_fp16.h>
#include <cstdint>

#define CDIM 1024
#define TT   2048
#define BB   4
#define NH   16
#define HD   64
#define MROWS 8192          // BB*TT
#define NQKV  3072

#define QSCALE 0.18033688f  // 0.125 * log2(e): applied to S in attention (fp32)
#define WSCALE 32.0f        // weights pre-scaled x32 (keeps fp16 lo-residuals normal)
#define INV32  0.03125f

// ---------------- scratch (__device__ globals; allocation-free rule) --------
__device__ __align__(16) __half g_Xh[(size_t)MROWS*CDIM];
__device__ __align__(16) __half g_WQh[(size_t)NQKV*CDIM];
__device__ __align__(16) __half g_WQl[(size_t)NQKV*CDIM];
__device__ __align__(16) __half g_WPh[(size_t)CDIM*CDIM];
__device__ __align__(16) __half g_WPl[(size_t)CDIM*CDIM];
__device__ __align__(16) __half g_Qh[(size_t)BB*NH*TT*HD];
__device__ __align__(16) __half g_Ql[(size_t)BB*NH*TT*HD];
__device__ __align__(16) __half g_Kh[(size_t)BB*NH*TT*HD];
__device__ __align__(16) __half g_Kl[(size_t)BB*NH*TT*HD];
__device__ __align__(16) __half g_Vh[(size_t)BB*NH*TT*HD];
__device__ __align__(16) __half g_Vl[(size_t)BB*NH*TT*HD];
__device__ __align__(16) __half g_Ch[(size_t)MROWS*CDIM];

// ---------------- helpers ---------------------------------------------------
__device__ __forceinline__ void mma16816h(float* c, const unsigned* a, const unsigned* b)
{
    asm volatile(
        "mma.sync.aligned.m16n8k16.row.col.f32.f16.f16.f32 "
        "{%0,%1,%2,%3}, {%4,%5,%6,%7}, {%8,%9}, {%0,%1,%2,%3};\n"
        : "+f"(c[0]), "+f"(c[1]), "+f"(c[2]), "+f"(c[3])
        : "r"(a[0]), "r"(a[1]), "r"(a[2]), "r"(a[3]), "r"(b[0]), "r"(b[1]));
}

#define LDSM4(rg, addr) \
    asm volatile("ldmatrix.sync.aligned.m8n8.x4.shared.b16 {%0,%1,%2,%3}, [%4];" \
                 : "=r"((rg)[0]), "=r"((rg)[1]), "=r"((rg)[2]), "=r"((rg)[3]) : "r"(addr))
#define LDSM2(rg, addr) \
    asm volatile("ldmatrix.sync.aligned.m8n8.x2.shared.b16 {%0,%1}, [%2];" \
                 : "=r"((rg)[0]), "=r"((rg)[1]) : "r"(addr))
#define LDSM2T(rg, addr) \
    asm volatile("ldmatrix.sync.aligned.m8n8.x2.trans.shared.b16 {%0,%1}, [%2];" \
                 : "=r"((rg)[0]), "=r"((rg)[1]) : "r"(addr))
#define CP16(dst, src) \
    asm volatile("cp.async.cg.shared.global [%0], [%1], 16;" :: "r"(dst), "l"(src))
#define CP_COMMIT() asm volatile("cp.async.commit_group;" ::: "memory")

// pack two floats into fp16x2 hi part, return fp16x2 lo-residual via out param
__device__ __forceinline__ unsigned pack_hl_h(float a, float b, unsigned& lo)
{
    __half2 h = __floats2half2_rn(a, b);
    float ra = a - __half2float(h.x);
    float rb = b - __half2float(h.y);
    __half2 l = __floats2half2_rn(ra, rb);
    lo = *reinterpret_cast<unsigned*>(&l);
    return *reinterpret_cast<unsigned*>(&h);
}

__device__ __forceinline__ unsigned pack_h(float a, float b)
{
    __half2 h = __floats2half2_rn(a, b);
    return *reinterpret_cast<unsigned*>(&h);
}

// ---------------- splits -----------------------------------------------------
// x: fp32 -> fp16 (hi only; A-residual is dropped by the 2-pass GEMM scheme)
__global__ __launch_bounds__(256)
void split1_kernel(const float* __restrict__ src, __half* __restrict__ hi, int n4)
{
    int i = blockIdx.x * 256 + threadIdx.x;
    if (i >= n4) return;
    float4 v = ((const float4*)src)[i];
    ((uint2*)hi)[i] = make_uint2(pack_h(v.x, v.y), pack_h(v.z, v.w));
}

// w: fp32*32 -> fp16 hi/lo (scaled so lo residuals stay in fp16 normal range)
__global__ __launch_bounds__(256)
void split2_kernel(const float* __restrict__ src, __half* __restrict__ hi,
                   __half* __restrict__ lo, int n4)
{
    int i = blockIdx.x * 256 + threadIdx.x;
    if (i >= n4) return;
    float4 v = ((const float4*)src)[i];
    unsigned l0, l1;
    unsigned h0 = pack_hl_h(v.x * WSCALE, v.y * WSCALE, l0);
    unsigned h1 = pack_hl_h(v.z * WSCALE, v.w * WSCALE, l1);
    ((uint2*)hi)[i] = make_uint2(h0, h1);
    ((uint2*)lo)[i] = make_uint2(l0, l1);
}

// ---------------- GEMM: C[m,n] = sum_k A[m,k]*W[n,k]  (fp16 2-pass mma) -----
// 128x128x32 tile, 256 threads, 2 CTAs/SM, cp.async 2-stage, single barrier.
// Stage layout (elements): Ah@0, Bh@5120, Bl@10240; stage stride 15360 (30720B).
#define GSTG 15360

template<int MODE>
__device__ __forceinline__ void gemm_load_tile(
    unsigned sb, int so,
    const __half* Ah, const __half* Bh, const __half* Bl,
    int m0, int n0, int kt, int tid)
{
    #pragma unroll
    for (int r = 0; r < 2; r++) {
        int c = tid + r * 256;          // 512 16B-chunks (128 rows x 4)
        int row = c >> 2, c4 = c & 3;
        size_t ga = (size_t)(m0 + row) * CDIM + kt + c4 * 8;
        size_t gb = (size_t)(n0 + row) * CDIM + kt + c4 * 8;
        unsigned d = sb + 2u * (so + row * 40 + c4 * 8);
        CP16(d,              Ah + ga);
        CP16(d + 2u * 5120,  Bh + gb);
        CP16(d + 2u * 10240, Bl + gb);
    }
    CP_COMMIT();
}

template<int MODE>
__global__ __launch_bounds__(256, 2)
void gemm_mma_kernel(float* __restrict__ Cout)
{
    extern __shared__ __half dsm[];
    const unsigned sb = (unsigned)__cvta_generic_to_shared(dsm);

    const __half* Ah = (MODE == 0) ? g_Xh  : g_Ch;
    const __half* Bh = (MODE == 0) ? g_WQh : g_WPh;
    const __half* Bl = (MODE == 0) ? g_WQl : g_WPl;

    const int tid  = threadIdx.x;
    const int lane = tid & 31;
    const int wrp  = tid >> 5;          // 0..7
    const int g    = lane >> 2;         // 0..7
    const int tig  = lane & 3;          // 0..3
    const int wm   = wrp >> 2;          // 0..1 (64 rows each)
    const int wn   = wrp & 3;           // 0..3 (32 cols each)
    const int m0   = blockIdx.y * 128;
    const int n0   = blockIdx.x * 128;

    // ldmatrix.x4 per-lane offsets (elements within a stage array)
    const int a_off = (wm * 64 + (lane & 15)) * 40 + 8 * ((lane >> 4) & 1);
    const int b_off = (wn * 32 + (lane & 15)) * 40 + 8 * ((lane >> 4) & 1);

    float acc[4][4][4];
    #pragma unroll
    for (int a = 0; a < 4; a++)
        #pragma unroll
        for (int b = 0; b < 4; b++)
            #pragma unroll
            for (int c = 0; c < 4; c++) acc[a][b][c] = 0.f;

    gemm_load_tile<MODE>(sb, 0, Ah, Bh, Bl, m0, n0, 0, tid);

    #pragma unroll 1
    for (int t = 0; t < CDIM / 32; t++) {
        asm volatile("cp.async.wait_group 0;" ::: "memory");
        __syncthreads();
        if (t < CDIM / 32 - 1)
            gemm_load_tile<MODE>(sb, ((t + 1) & 1) * GSTG, Ah, Bh, Bl,
                                 m0, n0, (t + 1) * 32, tid);
        const int so = (t & 1) * GSTG;
        #pragma unroll
        for (int kk = 0; kk < 32; kk += 16) {
            // B fragments (hi & lo): ldmatrix.x4 covers 2 n-tiles x both k-halves
            unsigned bfh[4][2], bfl[4][2];
            #pragma unroll
            for (int p = 0; p < 2; p++) {
                unsigned r[4], rl[4];
                unsigned baddr = sb + 2u * (so + 5120 + b_off + p * 640 + kk);
                LDSM4(r,  baddr);
                LDSM4(rl, baddr + 2u * 5120);
                bfh[2*p][0] = r[0];  bfh[2*p+1][0] = r[1];
                bfh[2*p][1] = r[2];  bfh[2*p+1][1] = r[3];
                bfl[2*p][0] = rl[0]; bfl[2*p+1][0] = rl[1];
                bfl[2*p][1] = rl[2]; bfl[2*p+1][1] = rl[3];
            }
            // A hi fragments for all mt, then 2 pass-outer MMA sweeps
            unsigned afh[4][4];
            #pragma unroll
            for (int mt = 0; mt < 4; mt++) {
                unsigned aaddr = sb + 2u * (so + a_off + mt * 640 + kk);
                LDSM4(afh[mt], aaddr);
            }
            #pragma unroll
            for (int mt = 0; mt < 4; mt++)
                #pragma unroll
                for (int nt = 0; nt < 4; nt++)
                    mma16816h(acc[mt][nt], afh[mt], bfh[nt]);
            #pragma unroll
            for (int mt = 0; mt < 4; mt++)
                #pragma unroll
                for (int nt = 0; nt < 4; nt++)
                    mma16816h(acc[mt][nt], afh[mt], bfl[nt]);
        }
    }

    // ---------------- epilogue (undo WSCALE via INV32) ----------------
    #pragma unroll
    for (int mt = 0; mt < 4; mt++) {
        int row = m0 + wm * 64 + mt * 16 + g;       // row g; row+8 for c2/c3
        #pragma unroll
        for (int nt = 0; nt < 4; nt++) {
            int n = n0 + wn * 32 + nt * 8 + 2 * tig;
            float v0 = acc[mt][nt][0] * INV32, v1 = acc[mt][nt][1] * INV32;
            float v2 = acc[mt][nt][2] * INV32, v3 = acc[mt][nt][3] * INV32;
            if (MODE == 1) {
                *(float2*)(Cout + (size_t)row * CDIM + n)       = make_float2(v0, v1);
                *(float2*)(Cout + (size_t)(row + 8) * CDIM + n) = make_float2(v2, v3);
            } else {
                int part = n >> 10;                 // 0=q 1=k 2=v
                int cc   = n & (CDIM - 1);
                int h    = cc >> 6;
                int d    = cc & 63;
                int b    = row >> 11;
                int tq   = row & (TT - 1);
                __half* dh = (part == 0) ? g_Qh : (part == 1) ? g_Kh : g_Vh;
                __half* dl = (part == 0) ? g_Ql : (part == 1) ? g_Kl : g_Vl;
                size_t base = (((size_t)(b * NH + h)) * TT + tq) * HD + d;
                unsigned lp;
                unsigned hp = pack_hl_h(v0, v1, lp);
                *(unsigned*)(dh + base) = hp;  *(unsigned*)(dl + base) = lp;
                hp = pack_hl_h(v2, v3, lp);
                *(unsigned*)(dh + base + 8 * HD) = hp;  *(unsigned*)(dl + base + 8 * HD) = lp;
            }
        }
    }
}

// ---------------- causal flash attention (fp16x3 mma, R8 structure) ---------
// grid = (16 qtiles of 128 rows, 64 bh). 256 threads (8 warps, 16 q-rows each).
// Q/K unscaled; S is scaled by QSCALE in fp32, softmax in base-2 (exp2f).
__global__ __launch_bounds__(256)
void attn_mma_kernel()
{
    __shared__ __align__(16) __half Khs[64][72];
    __shared__ __align__(16) __half Kls[64][72];
    __shared__ __align__(16) __half Vhs[64][72];
    __shared__ __align__(16) __half Vls[64][72];

    const int tid  = threadIdx.x;
    const int lane = tid & 31;
    const int wrp  = tid >> 5;                  // 0..7
    const int g    = lane >> 2;
    const int tig  = lane & 3;
    const int qt   = (int)gridDim.x - 1 - (int)blockIdx.x;   // heavy tiles first
    const int bh   = blockIdx.y;
    const int qg0  = qt * 128 + 16 * wrp + g;
    const int qg1  = qg0 + 8;

    const size_t hb = (size_t)bh * TT * HD;

    const int k_off = (lane & 7) * 72 + 8 * ((lane >> 3) & 1);
    const unsigned khs_b = (unsigned)__cvta_generic_to_shared(&Khs[0][0]);
    const unsigned kls_b = (unsigned)__cvta_generic_to_shared(&Kls[0][0]);

    unsigned qh[4][4], ql[4][4];
    {
        const __half* Qhp = g_Qh + hb;
        const __half* Qlp = g_Ql + hb;
        #pragma unroll
        for (int kt = 0; kt < 4; kt++) {
            size_t r0 = (size_t)qg0 * HD + 16 * kt + 2 * tig;
            size_t r1 = (size_t)qg1 * HD + 16 * kt + 2 * tig;
            qh[kt][0] = *(const unsigned*)(Qhp + r0);
            qh[kt][1] = *(const unsigned*)(Qhp + r1);
            qh[kt][2] = *(const unsigned*)(Qhp + r0 + 8);
            qh[kt][3] = *(const unsigned*)(Qhp + r1 + 8);
            ql[kt][0] = *(const unsigned*)(Qlp + r0);
            ql[kt][1] = *(const unsigned*)(Qlp + r1);
            ql[kt][2] = *(const unsigned*)(Qlp + r0 + 8);
            ql[kt][3] = *(const unsigned*)(Qlp + r1 + 8);
        }
    }

    float oacc[8][4];
    #pragma unroll
    for (int nt = 0; nt < 8; nt++)
        #pragma unroll
        for (int c = 0; c < 4; c++) oacc[nt][c] = 0.f;
    float m0r = -1e30f, m1r = -1e30f, l0r = 0.f, l1r = 0.f;

    const int ntiles = 2 * qt + 2;
    for (int jt = 0; jt < ntiles; jt++) {
        const int j0 = jt * 64;
        __syncthreads();
        #pragma unroll
        for (int r = 0; r < 2; r++) {
            int c   = tid + r * 256;            // 0..511
            int row = c >> 3, c4 = c & 7;
            size_t go = hb + (size_t)(j0 + row) * HD + c4 * 8;
            *(uint4*)&Khs[row][c4 * 8] = *(const uint4*)(g_Kh + go);
            *(uint4*)&Kls[row][c4 * 8] = *(const uint4*)(g_Kl + go);
            *(uint4*)&Vhs[row][c4 * 8] = *(const uint4*)(g_Vh + go);
            *(uint4*)&Vls[row][c4 * 8] = *(const uint4*)(g_Vl + go);
        }
        __syncthreads();

        // ---- S = Q K^T (3-pass hi/lo, fp16) ----
        float sacc[8][4];
        #pragma unroll
        for (int nt = 0; nt < 8; nt++)
            #pragma unroll
            for (int c = 0; c < 4; c++) sacc[nt][c] = 0.f;

        #pragma unroll
        for (int kt = 0; kt < 4; kt++) {
            unsigned khf[8][2], klf[8][2];
            #pragma unroll
            for (int nt = 0; nt < 8; nt++) {
                unsigned a = 2u * (k_off + nt * 576 + 16 * kt);
                LDSM2(khf[nt], khs_b + a);
                LDSM2(klf[nt], kls_b + a);
            }
            #pragma unroll
            for (int nt = 0; nt < 8; nt++) mma16816h(sacc[nt], qh[kt], khf[nt]);
            #pragma unroll
            for (int nt = 0; nt < 8; nt++) mma16816h(sacc[nt], qh[kt], klf[nt]);
            #pragma unroll
            for (int nt = 0; nt < 8; nt++) mma16816h(sacc[nt], ql[kt], khf[nt]);
        }

        // ---- softmax scale (log2-units) then causal mask ----
        #pragma unroll
        for (int nt = 0; nt < 8; nt++) {
            sacc[nt][0] *= QSCALE; sacc[nt][1] *= QSCALE;
            sacc[nt][2] *= QSCALE; sacc[nt][3] *= QSCALE;
        }
        if (j0 + 63 > qt * 128 + 16 * wrp) {
            #pragma unroll
            for (int nt = 0; nt < 8; nt++) {
                int jg = j0 + 8 * nt + 2 * tig;
                if (jg     > qg0) sacc[nt][0] = -1e30f;
                if (jg + 1 > qg0) sacc[nt][1] = -1e30f;
                if (jg     > qg1) sacc[nt][2] = -1e30f;
                if (jg + 1 > qg1) sacc[nt][3] = -1e30f;
            }
        }

        // ---- online softmax (base-2; per-row, quad shuffles) ----
        float t0 = -1e30f, t1 = -1e30f;
        #pragma unroll
        for (int nt = 0; nt < 8; nt++) {
            t0 = fmaxf(t0, fmaxf(sacc[nt][0], sacc[nt][1]));
            t1 = fmaxf(t1, fmaxf(sacc[nt][2], sacc[nt][3]));
        }
        t0 = fmaxf(t0, __shfl_xor_sync(0xffffffffu, t0, 1));
        t0 = fmaxf(t0, __shfl_xor_sync(0xffffffffu, t0, 2));
        t1 = fmaxf(t1, __shfl_xor_sync(0xffffffffu, t1, 1));
        t1 = fmaxf(t1, __shfl_xor_sync(0xffffffffu, t1, 2));
        float mn0 = fmaxf(m0r, t0), mn1 = fmaxf(m1r, t1);
        float al0 = exp2f(m0r - mn0), al1 = exp2f(m1r - mn1);
        m0r = mn0; m1r = mn1;
        #pragma unroll
        for (int nt = 0; nt < 8; nt++) {
            oacc[nt][0] *= al0; oacc[nt][1] *= al0;
            oacc[nt][2] *= al1; oacc[nt][3] *= al1;
        }

        // ---- P = exp2(S-m): A-fragments in-register (hi & lo fp16) ----
        unsigned ph[4][4], pl[4][4];
        float rs0 = 0.f, rs1 = 0.f;
        #pragma unroll
        for (int kt = 0; kt < 4; kt++) {
            float p00 = exp2f(sacc[2*kt    ][0] - mn0);
            float p01 = exp2f(sacc[2*kt    ][1] - mn0);
            float p02 = exp2f(sacc[2*kt    ][2] - mn1);
            float p03 = exp2f(sacc[2*kt    ][3] - mn1);
            float p10 = exp2f(sacc[2*kt + 1][0] - mn0);
            float p11 = exp2f(sacc[2*kt + 1][1] - mn0);
            float p12 = exp2f(sacc[2*kt + 1][2] - mn1);
            float p13 = exp2f(sacc[2*kt + 1][3] - mn1);
            rs0 += (p00 + p01) + (p10 + p11);
            rs1 += (p02 + p03) + (p12 + p13);
            ph[kt][0] = pack_hl_h(p00, p01, pl[kt][0]);
            ph[kt][1] = pack_hl_h(p02, p03, pl[kt][1]);
            ph[kt][2] = pack_hl_h(p10, p11, pl[kt][2]);
            ph[kt][3] = pack_hl_h(p12, p13, pl[kt][3]);
        }
        rs0 += __shfl_xor_sync(0xffffffffu, rs0, 1);
        rs0 += __shfl_xor_sync(0xffffffffu, rs0, 2);
        rs1 += __shfl_xor_sync(0xffffffffu, rs1, 1);
        rs1 += __shfl_xor_sync(0xffffffffu, rs1, 2);
        l0r = l0r * al0 + rs0;
        l1r = l1r * al1 + rs1;

        // ---- O += P @ V  (3-pass hi/lo, fp16) ----
        #pragma unroll
        for (int kt = 0; kt < 4; kt++) {
            unsigned vbh[8][2], vbl[8][2];
            int vrow = 16 * kt + (lane & 15);
            #pragma unroll
            for (int nt = 0; nt < 8; nt++) {
                LDSM2T(vbh[nt], (unsigned)__cvta_generic_to_shared(&Vhs[vrow][8 * nt]));
                LDSM2T(vbl[nt], (unsigned)__cvta_generic_to_shared(&Vls[vrow][8 * nt]));
            }
            #pragma unroll
            for (int nt = 0; nt < 8; nt++) mma16816h(oacc[nt], ph[kt], vbh[nt]);
            #pragma unroll
            for (int nt = 0; nt < 8; nt++) mma16816h(oacc[nt], ph[kt], vbl[nt]);
            #pragma unroll
            for (int nt = 0; nt < 8; nt++) mma16816h(oacc[nt], pl[kt], vbh[nt]);
        }
    }

    // ---- epilogue: O/l -> Ctx fp16 (hi only; proj drops A-residual) --------
    const float inv0 = 1.0f / l0r, inv1 = 1.0f / l1r;
    const int b = bh >> 4, h = bh & 15;
    size_t crow0 = ((size_t)(b * TT + qg0)) * CDIM + h * HD;
    size_t crow1 = ((size_t)(b * TT + qg1)) * CDIM + h * HD;
    #pragma unroll
    for (int nt = 0; nt < 8; nt++) {
        int d = 8 * nt + 2 * tig;
        *(unsigned*)(g_Ch + crow0 + d) = pack_h(oacc[nt][0] * inv0, oacc[nt][1] * inv0);
        *(unsigned*)(g_Ch + crow1 + d) = pack_h(oacc[nt][2] * inv1, oacc[nt][3] * inv1);
    }
}

// ---------------------------------------------------------------------------
extern "C" void kernel_launch(void* const* d_in, const int* in_sizes, int n_in,
                              void* d_out, int out_size)
{
    const float* x      = (const float*)d_in[0];  // [4,2048,1024]
    const float* w_qkv  = (const float*)d_in[1];  // [3072,1024]
    const float* w_proj = (const float*)d_in[2];  // [1024,1024]
    float* out = (float*)d_out;                   // [4,2048,1024] fp32

    __half *xh, *wqh, *wql, *wph, *wpl;
    cudaGetSymbolAddress((void**)&xh,  g_Xh);
    cudaGetSymbolAddress((void**)&wqh, g_WQh); cudaGetSymbolAddress((void**)&wql, g_WQl);
    cudaGetSymbolAddress((void**)&wph, g_WPh); cudaGetSymbolAddress((void**)&wpl, g_WPl);

    const int GEMM_SMEM = 2 * GSTG * 2;   // 61440 B
    cudaFuncSetAttribute(gemm_mma_kernel<0>,
                         cudaFuncAttributeMaxDynamicSharedMemorySize, GEMM_SMEM);
    cudaFuncSetAttribute(gemm_mma_kernel<1>,
                         cudaFuncAttributeMaxDynamicSharedMemorySize, GEMM_SMEM);

    // 1) splits: x -> fp16 hi; weights -> (w*32) fp16 hi/lo
    split1_kernel<<<(MROWS*CDIM/4 + 255)/256, 256>>>(x,      xh,  MROWS*CDIM/4);
    split2_kernel<<<(NQKV*CDIM/4  + 255)/256, 256>>>(w_qkv,  wqh, wql, NQKV*CDIM/4);
    split2_kernel<<<(CDIM*CDIM/4  + 255)/256, 256>>>(w_proj, wph, wpl, CDIM*CDIM/4);

    // 2) QKV projection (fp16 2-pass) -> Q/K/V hi/lo [bh,T,64] (unscaled)
    gemm_mma_kernel<0><<<dim3(NQKV/128, MROWS/128), 256, GEMM_SMEM>>>(nullptr);

    // 3) causal flash attention (fp16 3-pass) -> Ctx fp16
    attn_mma_kernel<<<dim3(TT/128, BB*NH), 256>>>();

    // 4) output projection (fp16 2-pass) -> fp32 out
    gemm_mma_kernel<1><<<dim3(CDIM/128, MROWS/128), 256, GEMM_SMEM>>>(out);
}

// round 17
// speedup vs baseline: 1.9008x; 1.9008x over previous
#include <cuda_runtime.h>
#include <cstdint>

#define CDIM 1024
#define TT   2048
#define BB   4
#define NH   16
#define HD   64
#define MROWS 8192          // BB*TT
#define NQKV  3072
#define QSCALE 0.18033688f  // 0.125 * log2(e): folded into Q at QKV epilogue

// ---------------- scratch (__device__ globals; allocation-free rule) --------
__device__ __align__(16) float g_X [(size_t)MROWS*CDIM];   // x, tf32-rounded
__device__ __align__(16) float g_WQ[(size_t)NQKV*CDIM];    // w_qkv, tf32-rounded
__device__ __align__(16) float g_WP[(size_t)CDIM*CDIM];    // w_proj, tf32-rounded
__device__ __align__(16) float g_Q [(size_t)BB*NH*TT*HD];  // [bh][t][d]
__device__ __align__(16) float g_K [(size_t)BB*NH*TT*HD];  // [bh][t][d]
__device__ __align__(16) float g_V [(size_t)BB*NH*TT*HD];  // [bh][d][t]  (transposed!)
__device__ __align__(16) float g_C [(size_t)MROWS*CDIM];   // ctx, tf32-rounded

// ---------------- helpers ---------------------------------------------------
__device__ __forceinline__ void mma_tf32(float* c, const unsigned* a, const unsigned* b)
{
    asm volatile(
        "mma.sync.aligned.m16n8k8.row.col.f32.tf32.tf32.f32 "
        "{%0,%1,%2,%3}, {%4,%5,%6,%7}, {%8,%9}, {%0,%1,%2,%3};\n"
        : "+f"(c[0]), "+f"(c[1]), "+f"(c[2]), "+f"(c[3])
        : "r"(a[0]), "r"(a[1]), "r"(a[2]), "r"(a[3]), "r"(b[0]), "r"(b[1]));
}

__device__ __forceinline__ unsigned cvt_rna(float x)
{
    unsigned u; asm("cvt.rna.tf32.f32 %0, %1;" : "=r"(u) : "f"(x)); return u;
}

#define LDSM4(rg, addr) \
    asm volatile("ldmatrix.sync.aligned.m8n8.x4.shared.b16 {%0,%1,%2,%3}, [%4];" \
                 : "=r"((rg)[0]), "=r"((rg)[1]), "=r"((rg)[2]), "=r"((rg)[3]) : "r"(addr))
#define CP16(dst, src) \
    asm volatile("cp.async.cg.shared.global [%0], [%1], 16;" :: "r"(dst), "l"(src))
#define CP_COMMIT() asm volatile("cp.async.commit_group;" ::: "memory")
#define CP_WAIT0()  asm volatile("cp.async.wait_group 0;" ::: "memory")

// ---------------- tf32 rounding pass ----------------------------------------
__global__ __launch_bounds__(256)
void cvt_kernel(const float* __restrict__ src, float* __restrict__ dst, int n4)
{
    int i = blockIdx.x * 256 + threadIdx.x;
    if (i >= n4) return;
    float4 v = ((const float4*)src)[i];
    uint4 o;
    o.x = cvt_rna(v.x); o.y = cvt_rna(v.y); o.z = cvt_rna(v.z); o.w = cvt_rna(v.w);
    ((uint4*)dst)[i] = o;
}

// ============================================================================
// tf32 GEMM: C[m,n] = sum_k A[m,k]*W[n,k]. 128x128x32 tile, 256 thr, 2 CTAs/SM.
// smem stage (fp32 elems): A[128][44] @0, B[128][44] @5632; stage = 11264 elems.
// Row pad 44 fp32 (176B): ldmatrix rows hit banks r*12 mod 32 -> conflict-free.
// ============================================================================
#define GPAD 44
#define GSTG (128 * GPAD * 2)   // 11264 fp32 per stage (45056 B)

__device__ __forceinline__ void gemm_load(
    unsigned sb, int so, const float* A, const float* B, int m0, int n0, int kt, int tid)
{
    #pragma unroll
    for (int r = 0; r < 4; r++) {
        int c = tid + r * 256;          // 0..1023 16B-chunks per array
        int row = c >> 3, c8 = c & 7;   // 8 chunks per 32-fp32 row
        size_t ga = (size_t)(m0 + row) * CDIM + kt + c8 * 4;
        size_t gb = (size_t)(n0 + row) * CDIM + kt + c8 * 4;
        unsigned d = sb + 4u * (unsigned)(so + row * GPAD + c8 * 4);
        CP16(d,                A + ga);
        CP16(d + 4u * 5632u,   B + gb);
    }
    CP_COMMIT();
}

template<int MODE>
__global__ __launch_bounds__(256, 2)
void gemm_tf32_kernel(float* __restrict__ Cout)
{
    extern __shared__ float dsm[];
    const unsigned sb = (unsigned)__cvta_generic_to_shared(dsm);

    const float* A = (MODE == 0) ? g_X  : g_C;
    const float* B = (MODE == 0) ? g_WQ : g_WP;

    const int tid  = threadIdx.x;
    const int lane = tid & 31;
    const int wrp  = tid >> 5;          // 0..7
    const int g    = lane >> 2;         // 0..7
    const int tig  = lane & 3;          // 0..3
    const int wm   = wrp >> 2;          // 0..1 (64 rows each)
    const int wn   = wrp & 3;           // 0..3 (32 cols each)
    const int m0   = blockIdx.y * 128;
    const int n0   = blockIdx.x * 128;

    // ldmatrix per-lane offsets (fp32 elements within stage)
    // A x4: lanes 0-15 rows 0-15 col-grp lo, 16-31 rows 0-15 col-grp hi
    const int a_off = (wm * 64 + (lane & 15)) * GPAD + ((lane >> 4) & 1) * 4;
    // B x4 (2 n-octs): lanes 0-7 r0-7 lo, 8-15 r0-7 hi, 16-23 r8-15 lo, 24-31 r8-15 hi
    const int b_off = (wn * 32 + ((lane >> 4) & 1) * 8 + (lane & 7)) * GPAD
                    + ((lane >> 3) & 1) * 4;

    float acc[4][4][4];
    #pragma unroll
    for (int a = 0; a < 4; a++)
        #pragma unroll
        for (int b = 0; b < 4; b++)
            #pragma unroll
            for (int c = 0; c < 4; c++) acc[a][b][c] = 0.f;

    gemm_load(sb, 0, A, B, m0, n0, 0, tid);

    #pragma unroll 1
    for (int t = 0; t < CDIM / 32; t++) {
        CP_WAIT0();
        __syncthreads();
        if (t < CDIM / 32 - 1)
            gemm_load(sb, ((t + 1) & 1) * GSTG, A, B, m0, n0, (t + 1) * 32, tid);
        const int so = (t & 1) * GSTG;
        #pragma unroll
        for (int s = 0; s < 4; s++) {           // four k8 steps per 32-chunk
            unsigned bf[2][4];
            #pragma unroll
            for (int p = 0; p < 2; p++)
                LDSM4(bf[p], sb + 4u * (unsigned)(so + 5632 + b_off + p * 16 * GPAD + s * 8));
            #pragma unroll
            for (int mt = 0; mt < 4; mt++) {
                unsigned af[4];
                LDSM4(af, sb + 4u * (unsigned)(so + a_off + mt * 16 * GPAD + s * 8));
                mma_tf32(acc[mt][0], af, &bf[0][0]);
                mma_tf32(acc[mt][1], af, &bf[0][2]);
                mma_tf32(acc[mt][2], af, &bf[1][0]);
                mma_tf32(acc[mt][3], af, &bf[1][2]);
            }
        }
    }

    // ---------------- epilogue ----------------
    #pragma unroll
    for (int mt = 0; mt < 4; mt++) {
        int row = m0 + wm * 64 + mt * 16 + g;       // rows g and g+8
        #pragma unroll
        for (int nt = 0; nt < 4; nt++) {
            int n = n0 + wn * 32 + nt * 8 + 2 * tig;
            float v0 = acc[mt][nt][0], v1 = acc[mt][nt][1];
            float v2 = acc[mt][nt][2], v3 = acc[mt][nt][3];
            if (MODE == 1) {
                *(float2*)(Cout + (size_t)row * CDIM + n)       = make_float2(v0, v1);
                *(float2*)(Cout + (size_t)(row + 8) * CDIM + n) = make_float2(v2, v3);
            } else {
                int part = n >> 10;                 // 0=q 1=k 2=v
                int cc   = n & (CDIM - 1);
                int h    = cc >> 6;
                int d    = cc & 63;
                int b    = row >> 11;
                int tq   = row & (TT - 1);
                int bh   = b * NH + h;
                if (part == 0) { v0 *= QSCALE; v1 *= QSCALE; v2 *= QSCALE; v3 *= QSCALE; }
                if (part == 2) {
                    // V transposed: [bh][d][t]
                    unsigned* vp = (unsigned*)g_V + ((size_t)bh * HD + d) * TT;
                    vp[tq]          = cvt_rna(v0);
                    vp[TT + tq]     = cvt_rna(v1);    // d+1
                    vp[tq + 8]      = cvt_rna(v2);    // t+8
                    vp[TT + tq + 8] = cvt_rna(v3);
                } else {
                    unsigned* dp = (unsigned*)((part == 0) ? g_Q : g_K)
                                 + ((size_t)bh * TT + tq) * HD + d;
                    *(uint2*)dp            = make_uint2(cvt_rna(v0), cvt_rna(v1));
                    *(uint2*)(dp + 8 * HD) = make_uint2(cvt_rna(v2), cvt_rna(v3));
                }
            }
        }
    }
}

// ============================================================================
// Causal flash attention, tf32 1-pass. grid = (16 qtiles of 128, 64 bh),
// 256 threads (8 warps x 16 q-rows). Q pre-scaled by 0.125*log2e -> exp2f.
// smem: 2 stages x { K[64][68] fp32, V^T[64][68] fp32 } = 69632 B.
// Pad 68 fp32 (272B): ldmatrix rows hit banks r*4 mod 32 -> conflict-free.
// ============================================================================
#define APAD 68
#define AKV  (64 * APAD)        // 4352 fp32 per array
#define ASTG (2 * AKV)          // 8704 fp32 per stage

__device__ __forceinline__ void attn_load_kv(
    unsigned sb, int st, size_t kb, size_t vb, int j0, int tid)
{
    #pragma unroll
    for (int r = 0; r < 4; r++) {
        int c = tid + r * 256;          // 0..1023 chunks per array
        int row = c >> 4, c16 = c & 15; // 16 chunks per 64-fp32 row
        unsigned d = sb + 4u * (unsigned)(st * ASTG + row * APAD + c16 * 4);
        CP16(d,             g_K + kb + (size_t)(j0 + row) * HD + c16 * 4);
        CP16(d + 4u * AKV,  g_V + vb + (size_t)row * TT + j0 + c16 * 4);
    }
    CP_COMMIT();
}

__global__ __launch_bounds__(256)
void attn_tf32_kernel()
{
    extern __shared__ float dsm[];
    const unsigned sb = (unsigned)__cvta_generic_to_shared(dsm);

    const int tid  = threadIdx.x;
    const int lane = tid & 31;
    const int wrp  = tid >> 5;                  // 0..7
    const int g    = lane >> 2;
    const int tig  = lane & 3;
    const int qt   = (int)gridDim.x - 1 - (int)blockIdx.x;   // heavy tiles first
    const int bh   = blockIdx.y;
    const int qg0  = qt * 128 + wrp * 16 + g;
    const int qg1  = qg0 + 8;

    const size_t kb = (size_t)bh * TT * HD;     // K base [t][d]
    const size_t vb = (size_t)bh * HD * TT;     // V base [d][t]

    // ---- stage Q tile (128x64) through smem, build A-frags ----
    {
        #pragma unroll
        for (int r = 0; r < 8; r++) {
            int c = tid + r * 256;              // 0..2047 chunks
            int row = c >> 4, c16 = c & 15;
            CP16(sb + 4u * (unsigned)(row * APAD + c16 * 4),
                 g_Q + kb + (size_t)(qt * 128 + row) * HD + c16 * 4);
        }
        CP_COMMIT(); CP_WAIT0(); __syncthreads();
    }
    unsigned q[8][4];
    {
        const int q_off = (wrp * 16 + (lane & 15)) * APAD + ((lane >> 4) & 1) * 4;
        #pragma unroll
        for (int s = 0; s < 8; s++)
            LDSM4(q[s], sb + 4u * (unsigned)(q_off + s * 8));
    }
    __syncthreads();    // everyone done reading Q before K/V overwrite stage 0

    // K/V x4 ldmatrix lane offset (2 row-octs per LDSM4)
    const int kv_off = (((lane >> 4) & 1) * 8 + (lane & 7)) * APAD + ((lane >> 3) & 1) * 4;

    float oacc[8][4];
    #pragma unroll
    for (int nt = 0; nt < 8; nt++)
        #pragma unroll
        for (int c = 0; c < 4; c++) oacc[nt][c] = 0.f;
    float m0r = -1e30f, m1r = -1e30f, l0r = 0.f, l1r = 0.f;

    const int ntiles = 2 * qt + 2;
    attn_load_kv(sb, 0, kb, vb, 0, tid);

    #pragma unroll 1
    for (int jt = 0; jt < ntiles; jt++) {
        const int j0 = jt * 64;
        CP_WAIT0();
        __syncthreads();
        if (jt + 1 < ntiles)
            attn_load_kv(sb, (jt + 1) & 1, kb, vb, j0 + 64, tid);
        const unsigned ksb = sb + 4u * (unsigned)((jt & 1) * ASTG);
        const unsigned vsb = ksb + 4u * (unsigned)AKV;

        // ---- S = Q K^T (tf32 1-pass: 8 k8-steps x 8 j-octs) ----
        float sacc[8][4];
        #pragma unroll
        for (int nt = 0; nt < 8; nt++)
            #pragma unroll
            for (int c = 0; c < 4; c++) sacc[nt][c] = 0.f;

        #pragma unroll
        for (int s = 0; s < 8; s++) {
            unsigned kf[4][4];
            #pragma unroll
            for (int p = 0; p < 4; p++)
                LDSM4(kf[p], ksb + 4u * (unsigned)(kv_off + p * 16 * APAD + s * 8));
            #pragma unroll
            for (int p = 0; p < 4; p++) {
                mma_tf32(sacc[2 * p],     q[s], &kf[p][0]);
                mma_tf32(sacc[2 * p + 1], q[s], &kf[p][2]);
            }
        }

        // ---- causal mask (only tiles touching the diagonal) ----
        if (j0 + 63 > qt * 128 + wrp * 16) {
            #pragma unroll
            for (int nt = 0; nt < 8; nt++) {
                int jg = j0 + 8 * nt + 2 * tig;
                if (jg     > qg0) sacc[nt][0] = -1e30f;
                if (jg + 1 > qg0) sacc[nt][1] = -1e30f;
                if (jg     > qg1) sacc[nt][2] = -1e30f;
                if (jg + 1 > qg1) sacc[nt][3] = -1e30f;
            }
        }

        // ---- online softmax (base-2; per-row, quad shuffles) ----
        float t0 = -1e30f, t1 = -1e30f;
        #pragma unroll
        for (int nt = 0; nt < 8; nt++) {
            t0 = fmaxf(t0, fmaxf(sacc[nt][0], sacc[nt][1]));
            t1 = fmaxf(t1, fmaxf(sacc[nt][2], sacc[nt][3]));
        }
        t0 = fmaxf(t0, __shfl_xor_sync(0xffffffffu, t0, 1));
        t0 = fmaxf(t0, __shfl_xor_sync(0xffffffffu, t0, 2));
        t1 = fmaxf(t1, __shfl_xor_sync(0xffffffffu, t1, 1));
        t1 = fmaxf(t1, __shfl_xor_sync(0xffffffffu, t1, 2));
        float mn0 = fmaxf(m0r, t0), mn1 = fmaxf(m1r, t1);
        float al0 = exp2f(m0r - mn0), al1 = exp2f(m1r - mn1);
        m0r = mn0; m1r = mn1;
        #pragma unroll
        for (int nt = 0; nt < 8; nt++) {
            oacc[nt][0] *= al0; oacc[nt][1] *= al0;
            oacc[nt][2] *= al1; oacc[nt][3] *= al1;
        }

        // ---- P = exp2(S-m), tf32-rounded; rowsums ----
        unsigned pu[8][4];
        float rs0 = 0.f, rs1 = 0.f;
        #pragma unroll
        for (int nt = 0; nt < 8; nt++) {
            float p0 = exp2f(sacc[nt][0] - mn0);
            float p1 = exp2f(sacc[nt][1] - mn0);
            float p2 = exp2f(sacc[nt][2] - mn1);
            float p3 = exp2f(sacc[nt][3] - mn1);
            pu[nt][0] = cvt_rna(p0); pu[nt][1] = cvt_rna(p1);
            pu[nt][2] = cvt_rna(p2); pu[nt][3] = cvt_rna(p3);
            rs0 += __uint_as_float(pu[nt][0]) + __uint_as_float(pu[nt][1]);
            rs1 += __uint_as_float(pu[nt][2]) + __uint_as_float(pu[nt][3]);
        }
        rs0 += __shfl_xor_sync(0xffffffffu, rs0, 1);
        rs0 += __shfl_xor_sync(0xffffffffu, rs0, 2);
        rs1 += __shfl_xor_sync(0xffffffffu, rs1, 1);
        rs1 += __shfl_xor_sync(0xffffffffu, rs1, 2);
        l0r = l0r * al0 + rs0;
        l1r = l1r * al1 + rs1;

        // ---- O += P @ V^T  (A-frags via quad shuffles from C-layout P) ----
        const int src1 = (lane & ~3) | (tig >> 1);
        const int src2 = src1 + 2;
        const bool odd = tig & 1;
        #pragma unroll
        for (int s = 0; s < 8; s++) {
            unsigned x0 = __shfl_sync(0xffffffffu, pu[s][0], src1);
            unsigned x1 = __shfl_sync(0xffffffffu, pu[s][1], src1);
            unsigned y0 = __shfl_sync(0xffffffffu, pu[s][2], src1);
            unsigned y1 = __shfl_sync(0xffffffffu, pu[s][3], src1);
            unsigned z0 = __shfl_sync(0xffffffffu, pu[s][0], src2);
            unsigned z1 = __shfl_sync(0xffffffffu, pu[s][1], src2);
            unsigned w0 = __shfl_sync(0xffffffffu, pu[s][2], src2);
            unsigned w1 = __shfl_sync(0xffffffffu, pu[s][3], src2);
            unsigned pa[4];
            pa[0] = odd ? x1 : x0;   // P(qg0, j0+8s+tig)
            pa[1] = odd ? y1 : y0;   // P(qg1, j0+8s+tig)
            pa[2] = odd ? z1 : z0;   // P(qg0, j0+8s+tig+4)
            pa[3] = odd ? w1 : w0;   // P(qg1, j0+8s+tig+4)
            unsigned vf[4][4];
            #pragma unroll
            for (int p = 0; p < 4; p++)
                LDSM4(vf[p], vsb + 4u * (unsigned)(kv_off + p * 16 * APAD + s * 8));
            #pragma unroll
            for (int p = 0; p < 4; p++) {
                mma_tf32(oacc[2 * p],     pa, &vf[p][0]);
                mma_tf32(oacc[2 * p + 1], pa, &vf[p][2]);
            }
        }
    }

    // ---- epilogue: O/l -> ctx (tf32-rounded fp32) ----
    const float inv0 = 1.0f / l0r, inv1 = 1.0f / l1r;
    const int b = bh >> 4, h = bh & 15;
    unsigned* c0p = (unsigned*)g_C + ((size_t)(b * TT + qg0)) * CDIM + h * HD;
    unsigned* c1p = (unsigned*)g_C + ((size_t)(b * TT + qg1)) * CDIM + h * HD;
    #pragma unroll
    for (int nt = 0; nt < 8; nt++) {
        int d = 8 * nt + 2 * tig;
        *(uint2*)(c0p + d) = make_uint2(cvt_rna(oacc[nt][0] * inv0),
                                        cvt_rna(oacc[nt][1] * inv0));
        *(uint2*)(c1p + d) = make_uint2(cvt_rna(oacc[nt][2] * inv1),
                                        cvt_rna(oacc[nt][3] * inv1));
    }
}

// ---------------------------------------------------------------------------
extern "C" void kernel_launch(void* const* d_in, const int* in_sizes, int n_in,
                              void* d_out, int out_size)
{
    const float* x      = (const float*)d_in[0];  // [4,2048,1024]
    const float* w_qkv  = (const float*)d_in[1];  // [3072,1024]
    const float* w_proj = (const float*)d_in[2];  // [1024,1024]
    float* out = (float*)d_out;                   // [4,2048,1024] fp32

    float *xp, *wqp, *wpp;
    cudaGetSymbolAddress((void**)&xp,  g_X);
    cudaGetSymbolAddress((void**)&wqp, g_WQ);
    cudaGetSymbolAddress((void**)&wpp, g_WP);

    const int GEMM_SMEM = 2 * GSTG * 4;           // 90112 B
    const int ATTN_SMEM = 2 * ASTG * 4;           // 69632 B
    cudaFuncSetAttribute(gemm_tf32_kernel<0>,
                         cudaFuncAttributeMaxDynamicSharedMemorySize, GEMM_SMEM);
    cudaFuncSetAttribute(gemm_tf32_kernel<1>,
                         cudaFuncAttributeMaxDynamicSharedMemorySize, GEMM_SMEM);
    cudaFuncSetAttribute(attn_tf32_kernel,
                         cudaFuncAttributeMaxDynamicSharedMemorySize, ATTN_SMEM);

    // 1) tf32-round inputs/weights (replaces all hi/lo split kernels)
    cvt_kernel<<<(MROWS*CDIM/4 + 255)/256, 256>>>(x,      xp,  MROWS*CDIM/4);
    cvt_kernel<<<(NQKV*CDIM/4  + 255)/256, 256>>>(w_qkv,  wqp, NQKV*CDIM/4);
    cvt_kernel<<<(CDIM*CDIM/4  + 255)/256, 256>>>(w_proj, wpp, CDIM*CDIM/4);

    // 2) QKV projection (tf32) -> Q(scaled)/K [bh][t][d], V [bh][d][t]
    gemm_tf32_kernel<0><<<dim3(NQKV/128, MROWS/128), 256, GEMM_SMEM>>>(nullptr);

    // 3) causal flash attention (tf32) -> ctx
    attn_tf32_kernel<<<dim3(TT/128, BB*NH), 256, ATTN_SMEM>>>();

    // 4) output projection (tf32) -> fp32 out
    gemm_tf32_kernel<1><<<dim3(CDIM/128, MROWS/128), 256, GEMM_SMEM>>>(out);
}